// round 8
// baseline (speedup 1.0000x reference)
#include <cuda_runtime.h>
#include <math.h>

#define BB 2
#define NN 512
#define DIN 512
#define DM 256
#define C2LOG2E 2.885390081777927f   // 2*log2(e)

// scratch (static device globals — no allocation)
__device__ float g_h[BB * NN * DM];    // h[b][n][d] = tanh(x@Wx+bx)
__device__ float g_p[BB * NN * DM];    // P row-major: exp2(c*(u+bp))
__device__ float g_qt[BB * DM * NN];   // Q transposed: exp2(-c*u)[b][d][n]

__device__ __forceinline__ float ex2_fast(float x) {
    float y; asm("ex2.approx.f32 %0, %1;" : "=f"(y) : "f"(x)); return y;
}
__device__ __forceinline__ float rcp_fast(float x) {
    float y; asm("rcp.approx.f32 %0, %1;" : "=f"(y) : "f"(x)); return y;
}

// ---------------------------------------------------------------------------
// Kernel U: pos projections only.  P = exp2(c*(u+bp)), Q^T = exp2(-c*u).
// grid = 256 blocks x 256 threads; block handles 8 rows, thread t = col d.
// ---------------------------------------------------------------------------
__global__ __launch_bounds__(256) void kU(const float* __restrict__ pos,
                                          const float* __restrict__ Wp,
                                          const float* __restrict__ bp) {
    const int t = threadIdx.x;
    const int row0 = blockIdx.x * 8;
    const float w0 = Wp[0 * DM + t], w1 = Wp[1 * DM + t];
    const float w2 = Wp[2 * DM + t], w3 = Wp[3 * DM + t];
    const float bpv = bp[t];
    const int b = row0 / NN;
    const int n0 = row0 % NN;
#pragma unroll
    for (int r = 0; r < 8; r++) {
        const float* p = pos + (row0 + r) * 4;
        float u = p[0] * w0 + p[1] * w1 + p[2] * w2 + p[3] * w3;
        g_p[(row0 + r) * DM + t] = ex2_fast(C2LOG2E * (u + bpv));
        g_qt[(b * DM + t) * NN + n0 + r] = ex2_fast(-C2LOG2E * u);
    }
}

// ---------------------------------------------------------------------------
// Kernel A (h only, split-K): h = tanh(x @ Wx + bx).
// 4 rows/block, K split across two thread-halves. grid = 256 x 512 threads.
// Runs on a SIDE stream concurrently with kU+kScore.
// ---------------------------------------------------------------------------
__global__ __launch_bounds__(512) void kA(const float* __restrict__ x,
                                          const float* __restrict__ Wx,
                                          const float* __restrict__ bx) {
    __shared__ float s_x[DIN][4];    // 8KB
    __shared__ float s_part[4][DM];  // 4KB
    const int t = threadIdx.x;
    const int row0 = blockIdx.x * 4;
    const int c  = t & (DM - 1);
    const int kh = t >> 8;

    for (int e = t; e < DIN * 4; e += 512) {
        int r = e >> 9, cc = e & (DIN - 1);
        s_x[cc][r] = x[(row0 + r) * DIN + cc];
    }
    __syncthreads();

    float a0 = 0.f, a1 = 0.f, a2 = 0.f, a3 = 0.f;
    const int kb = kh << 8;
#pragma unroll 8
    for (int k = 0; k < 256; k++) {
        float wv = Wx[(kb + k) * DM + c];
        float4 xv = *(const float4*)&s_x[kb + k][0];
        a0 += xv.x * wv; a1 += xv.y * wv;
        a2 += xv.z * wv; a3 += xv.w * wv;
    }
    if (kh) {
        s_part[0][c] = a0; s_part[1][c] = a1;
        s_part[2][c] = a2; s_part[3][c] = a3;
    }
    __syncthreads();
    if (!kh) {
        const float bias = bx[c];
        a0 += s_part[0][c] + bias;
        a1 += s_part[1][c] + bias;
        a2 += s_part[2][c] + bias;
        a3 += s_part[3][c] + bias;
        g_h[(row0 + 0) * DM + c] = tanhf(a0);
        g_h[(row0 + 1) * DM + c] = tanhf(a1);
        g_h[(row0 + 2) * DM + c] = tanhf(a2);
        g_h[(row0 + 3) * DM + c] = tanhf(a3);
    }
}

// ---------------------------------------------------------------------------
// Kernel Score (benched best): Block = 4 query rows x 256 j's.
// grid = 512 blocks, 256 threads. score = W - 2*sum_d w_d/(1+P_i[d]*Q_j[d])
// ---------------------------------------------------------------------------
__global__ __launch_bounds__(256) void kScore(const float* __restrict__ w,
                                              float* __restrict__ attn_out) {
    __shared__ float s_pi[DM][4];   // 4KB
    __shared__ float s_wn[DM];      // 1KB
    __shared__ float s_W;

    const int t = threadIdx.x;
    const int jt = blockIdx.x & 1;
    const int it = blockIdx.x >> 1;
    const int b  = it / (NN / 4);
    const int i0 = (it % (NN / 4)) * 4;
    const int j  = jt * 256 + t;

    if (t < DM) s_wn[t] = -2.0f * w[t];
    if (t < 32) {
        float s = 0.f;
#pragma unroll
        for (int k = 0; k < 8; k++) s += w[t + 32 * k];
#pragma unroll
        for (int o = 16; o; o >>= 1) s += __shfl_xor_sync(0xffffffffu, s, o);
        if (t == 0) s_W = s;
    }
    {
        const float* prow = g_p + (b * NN + i0) * DM;
        for (int e = t; e < 4 * DM; e += 256) {
            int r = e >> 8, d = e & (DM - 1);
            s_pi[d][r] = prow[r * DM + d];
        }
    }
    __syncthreads();
    const float W = s_W;

    float acc0 = 0.f, acc1 = 0.f, acc2 = 0.f, acc3 = 0.f;
    const float* qp = g_qt + b * DM * NN + j;
    float qbuf[4];
#pragma unroll
    for (int p = 0; p < 4; p++) qbuf[p] = qp[p * NN];

    for (int d0 = 0; d0 < DM; d0 += 4) {
        float qc[4];
#pragma unroll
        for (int p = 0; p < 4; p++) qc[p] = qbuf[p];
        if (d0 + 4 < DM) {
#pragma unroll
            for (int p = 0; p < 4; p++) qbuf[p] = qp[(d0 + 4 + p) * NN];
        }
#pragma unroll
        for (int dd = 0; dd < 4; dd++) {
            const int d = d0 + dd;
            const float wn = s_wn[d];
            const float4 pi = *(const float4*)&s_pi[d][0];
            const float qj = qc[dd];
            float de0 = fmaf(pi.x, qj, 1.0f);
            float de1 = fmaf(pi.y, qj, 1.0f);
            float de2 = fmaf(pi.z, qj, 1.0f);
            float de3 = fmaf(pi.w, qj, 1.0f);
            float r01 = rcp_fast(de0 * de1);
            float r23 = rcp_fast(de2 * de3);
            float w01 = wn * r01;
            float w23 = wn * r23;
            acc0 += w01 * de1;
            acc1 += w01 * de0;
            acc2 += w23 * de3;
            acc3 += w23 * de2;
        }
    }
    float* arow = attn_out + (b * NN + i0) * NN + j;
    arow[0 * NN] = W + acc0;
    arow[1 * NN] = W + acc1;
    arow[2 * NN] = W + acc2;
    arow[3 * NN] = W + acc3;
}

// ---------------------------------------------------------------------------
// Kernel SoftOut (benched best): masked softmax over 4 rows + output GEMM.
// grid = 256 blocks, 512 threads.
// ---------------------------------------------------------------------------
__global__ __launch_bounds__(512) void kSoftOut(const int* __restrict__ mask,
                                                float* __restrict__ out,
                                                float* __restrict__ attn_out) {
    __shared__ float s_attn[4][NN];

    const int t = threadIdx.x;
    const int blk = blockIdx.x;
    const int b = blk / (NN / 4);
    const int i0 = (blk % (NN / 4)) * 4;

    {
        const float4* src = (const float4*)(attn_out + (b * NN + i0) * NN);
        float4* dst = (float4*)&s_attn[0][0];
        for (int e = t; e < 4 * NN / 4; e += 512) dst[e] = src[e];
    }
    __syncthreads();

    const int wid = t >> 5, lane = t & 31;
    if (wid < 4) {
        const int i = i0 + wid;
        const int4* m4 = (const int4*)(mask + (b * NN + i) * NN);
        float4* s4 = (float4*)&s_attn[wid][0];
        int4 mv[4];
        float4 sv[4];
#pragma unroll
        for (int k = 0; k < 4; k++) {
            mv[k] = m4[lane + 32 * k];
            sv[k] = s4[lane + 32 * k];
        }
        float mx = -INFINITY;
#pragma unroll
        for (int k = 0; k < 4; k++) {
            if (mv[k].x) mx = fmaxf(mx, sv[k].x);
            if (mv[k].y) mx = fmaxf(mx, sv[k].y);
            if (mv[k].z) mx = fmaxf(mx, sv[k].z);
            if (mv[k].w) mx = fmaxf(mx, sv[k].w);
        }
#pragma unroll
        for (int o = 16; o; o >>= 1) mx = fmaxf(mx, __shfl_xor_sync(0xffffffffu, mx, o));
        float sum = 0.f;
#pragma unroll
        for (int k = 0; k < 4; k++) {
            sv[k].x = mv[k].x ? __expf(sv[k].x - mx) : 0.f;
            sv[k].y = mv[k].y ? __expf(sv[k].y - mx) : 0.f;
            sv[k].z = mv[k].z ? __expf(sv[k].z - mx) : 0.f;
            sv[k].w = mv[k].w ? __expf(sv[k].w - mx) : 0.f;
            sum += sv[k].x + sv[k].y + sv[k].z + sv[k].w;
        }
#pragma unroll
        for (int o = 16; o; o >>= 1) sum += __shfl_xor_sync(0xffffffffu, sum, o);
        const float inv = (sum > 0.f) ? 1.f / sum : 0.f;
        float4* arow4 = (float4*)(attn_out + (b * NN + i) * NN);
#pragma unroll
        for (int k = 0; k < 4; k++) {
            sv[k].x *= inv; sv[k].y *= inv; sv[k].z *= inv; sv[k].w *= inv;
            s4[lane + 32 * k] = sv[k];
            arow4[lane + 32 * k] = sv[k];
        }
    }
    __syncthreads();

    const int d = t & (DM - 1);
    const int half = t >> 8;
    float o0 = 0.f, o1 = 0.f;
    const float* hb = g_h + b * NN * DM + d;
    const float4* pA = (const float4*)&s_attn[2 * half][0];
    const float4* pB = (const float4*)&s_attn[2 * half + 1][0];
#pragma unroll 2
    for (int j4 = 0; j4 < NN / 4; j4++) {
        float4 a = pA[j4];
        float4 c = pB[j4];
        float h0 = hb[(4 * j4 + 0) * DM];
        float h1 = hb[(4 * j4 + 1) * DM];
        float h2 = hb[(4 * j4 + 2) * DM];
        float h3 = hb[(4 * j4 + 3) * DM];
        o0 += a.x * h0 + a.y * h1 + a.z * h2 + a.w * h3;
        o1 += c.x * h0 + c.y * h1 + c.z * h2 + c.w * h3;
    }
    out[(b * NN + i0 + 2 * half + 0) * DM + d] = o0;
    out[(b * NN + i0 + 2 * half + 1) * DM + d] = o1;
}

// ---------------------------------------------------------------------------
// Fork/join: kA (h) runs on a side stream concurrently with kU+kScore.
// Event-based fork/join is graph-capture legal and creates parallel branches.
// Host-side stream/event objects are created once (host resources only; the
// device work per call is identical and deterministic).
// ---------------------------------------------------------------------------
extern "C" void kernel_launch(void* const* d_in, const int* in_sizes, int n_in,
                              void* d_out, int out_size) {
    const float* x    = (const float*)d_in[0];  // [2,512,512]
    const float* pos  = (const float*)d_in[1];  // [2,512,4]
    const int*   mask = (const int*)  d_in[2];  // [2,512,512]
    const float* Wx   = (const float*)d_in[3];  // [512,256]
    const float* bx   = (const float*)d_in[4];  // [256]
    const float* Wp   = (const float*)d_in[5];  // [4,256]
    const float* bp   = (const float*)d_in[6];  // [256]
    const float* w    = (const float*)d_in[7];  // [256]

    float* out      = (float*)d_out;            // [2,512,256]
    float* attn_out = out + BB * NN * DM;       // [2,512,512]

    static cudaStream_t s_side = nullptr;
    static cudaEvent_t ev_fork = nullptr, ev_join = nullptr;
    if (s_side == nullptr) {
        cudaStreamCreateWithFlags(&s_side, cudaStreamNonBlocking);
        cudaEventCreateWithFlags(&ev_fork, cudaEventDisableTiming);
        cudaEventCreateWithFlags(&ev_join, cudaEventDisableTiming);
    }

    // fork: side stream inherits current position of the main (capture) stream
    cudaEventRecord(ev_fork, 0);
    cudaStreamWaitEvent(s_side, ev_fork, 0);

    // side branch: h projection (no dependency on kU/kScore)
    kA<<<BB * NN / 4, 512, 0, s_side>>>(x, Wx, bx);

    // main branch: pos projections -> scores
    kU<<<BB * NN / 8, 256>>>(pos, Wp, bp);
    kScore<<<(BB * NN / 4) * 2, 256>>>(w, attn_out);

    // join: kSoftOut needs both branches
    cudaEventRecord(ev_join, s_side);
    cudaStreamWaitEvent(0, ev_join, 0);

    kSoftOut<<<BB * NN / 4, 512>>>(mask, out, attn_out);
}

// round 9
// speedup vs baseline: 1.1165x; 1.1165x over previous
#include <cuda_runtime.h>
#include <math.h>

#define BB 2
#define NN 512
#define DIN 512
#define DM 256
#define C2LOG2E 2.885390081777927f   // 2*log2(e)

// scratch (static device globals — no allocation)
__device__ float g_h[BB * NN * DM];    // h[b][n][d] = tanh(x@Wx+bx)
__device__ float g_p[BB * NN * DM];    // P row-major: exp2(c*(u+bp))
__device__ float g_qt[BB * DM * NN];   // Q transposed: exp2(-c*u)[b][d][n]

__device__ __forceinline__ float ex2_fast(float x) {
    float y; asm("ex2.approx.f32 %0, %1;" : "=f"(y) : "f"(x)); return y;
}
__device__ __forceinline__ float rcp_fast(float x) {
    float y; asm("rcp.approx.f32 %0, %1;" : "=f"(y) : "f"(x)); return y;
}

// ---------------------------------------------------------------------------
// Kernel A: h = tanh(x @ Wx + bx), P/Q projections.
// 4 rows/block, K split 4-way across thread groups. grid 256 x 1024 threads.
// ---------------------------------------------------------------------------
__global__ __launch_bounds__(1024) void kA(const float* __restrict__ x,
                                           const float* __restrict__ pos,
                                           const float* __restrict__ Wx,
                                           const float* __restrict__ bx,
                                           const float* __restrict__ Wp,
                                           const float* __restrict__ bp) {
    __shared__ float s_x[DIN][4];        // 8KB
    __shared__ float s_part[3][4][DM];   // 12KB: partials from kq = 1,2,3
    const int t = threadIdx.x;
    const int row0 = blockIdx.x * 4;
    const int c  = t & (DM - 1);
    const int kq = t >> 8;               // K-quarter: 0..3

    for (int e = t; e < DIN * 4; e += 1024) {
        int r = e >> 9, cc = e & (DIN - 1);
        s_x[cc][r] = x[(row0 + r) * DIN + cc];
    }
    __syncthreads();

    float a0 = 0.f, a1 = 0.f, a2 = 0.f, a3 = 0.f;
    const int kb = kq << 7;
#pragma unroll 8
    for (int k = 0; k < 128; k++) {
        float wv = Wx[(kb + k) * DM + c];              // coalesced
        float4 xv = *(const float4*)&s_x[kb + k][0];   // broadcast LDS.128
        a0 += xv.x * wv; a1 += xv.y * wv;
        a2 += xv.z * wv; a3 += xv.w * wv;
    }
    if (kq) {
        s_part[kq - 1][0][c] = a0; s_part[kq - 1][1][c] = a1;
        s_part[kq - 1][2][c] = a2; s_part[kq - 1][3][c] = a3;
    }
    __syncthreads();
    if (kq == 0) {
        const float bias = bx[c];
        a0 += bias + s_part[0][0][c] + s_part[1][0][c] + s_part[2][0][c];
        a1 += bias + s_part[0][1][c] + s_part[1][1][c] + s_part[2][1][c];
        a2 += bias + s_part[0][2][c] + s_part[1][2][c] + s_part[2][2][c];
        a3 += bias + s_part[0][3][c] + s_part[1][3][c] + s_part[2][3][c];
        g_h[(row0 + 0) * DM + c] = tanhf(a0);
        g_h[(row0 + 1) * DM + c] = tanhf(a1);
        g_h[(row0 + 2) * DM + c] = tanhf(a2);
        g_h[(row0 + 3) * DM + c] = tanhf(a3);

        const int b = row0 / NN;
        const int n0 = row0 % NN;
        const float w0 = Wp[0 * DM + c], w1 = Wp[1 * DM + c];
        const float w2 = Wp[2 * DM + c], w3 = Wp[3 * DM + c];
        const float bpv = bp[c];
#pragma unroll
        for (int r = 0; r < 4; r++) {
            const float* p = pos + (row0 + r) * 4;
            float u = p[0] * w0 + p[1] * w1 + p[2] * w2 + p[3] * w3;
            g_p[(row0 + r) * DM + c] = ex2_fast(C2LOG2E * (u + bpv));
            g_qt[(b * DM + c) * NN + n0 + r] = ex2_fast(-C2LOG2E * u);
        }
    }
}

// ---------------------------------------------------------------------------
// Kernel Score (benched best, unchanged): 4 query rows x 256 j's per block.
// grid = 512 blocks, 256 threads. score = W - 2*sum_d w_d/(1+P_i[d]*Q_j[d])
// ---------------------------------------------------------------------------
__global__ __launch_bounds__(256) void kScore(const float* __restrict__ w,
                                              float* __restrict__ attn_out) {
    __shared__ float s_pi[DM][4];
    __shared__ float s_wn[DM];
    __shared__ float s_W;

    const int t = threadIdx.x;
    const int jt = blockIdx.x & 1;
    const int it = blockIdx.x >> 1;
    const int b  = it / (NN / 4);
    const int i0 = (it % (NN / 4)) * 4;
    const int j  = jt * 256 + t;

    if (t < DM) s_wn[t] = -2.0f * w[t];
    if (t < 32) {
        float s = 0.f;
#pragma unroll
        for (int k = 0; k < 8; k++) s += w[t + 32 * k];
#pragma unroll
        for (int o = 16; o; o >>= 1) s += __shfl_xor_sync(0xffffffffu, s, o);
        if (t == 0) s_W = s;
    }
    {
        const float* prow = g_p + (b * NN + i0) * DM;
        for (int e = t; e < 4 * DM; e += 256) {
            int r = e >> 8, d = e & (DM - 1);
            s_pi[d][r] = prow[r * DM + d];
        }
    }
    __syncthreads();
    const float W = s_W;

    float acc0 = 0.f, acc1 = 0.f, acc2 = 0.f, acc3 = 0.f;
    const float* qp = g_qt + b * DM * NN + j;
    float qbuf[4];
#pragma unroll
    for (int p = 0; p < 4; p++) qbuf[p] = qp[p * NN];

    for (int d0 = 0; d0 < DM; d0 += 4) {
        float qc[4];
#pragma unroll
        for (int p = 0; p < 4; p++) qc[p] = qbuf[p];
        if (d0 + 4 < DM) {
#pragma unroll
            for (int p = 0; p < 4; p++) qbuf[p] = qp[(d0 + 4 + p) * NN];
        }
#pragma unroll
        for (int dd = 0; dd < 4; dd++) {
            const int d = d0 + dd;
            const float wn = s_wn[d];
            const float4 pi = *(const float4*)&s_pi[d][0];
            const float qj = qc[dd];
            float de0 = fmaf(pi.x, qj, 1.0f);
            float de1 = fmaf(pi.y, qj, 1.0f);
            float de2 = fmaf(pi.z, qj, 1.0f);
            float de3 = fmaf(pi.w, qj, 1.0f);
            float r01 = rcp_fast(de0 * de1);
            float r23 = rcp_fast(de2 * de3);
            float w01 = wn * r01;
            float w23 = wn * r23;
            acc0 += w01 * de1;
            acc1 += w01 * de0;
            acc2 += w23 * de3;
            acc3 += w23 * de2;
        }
    }
    float* arow = attn_out + (b * NN + i0) * NN + j;
    arow[0 * NN] = W + acc0;
    arow[1 * NN] = W + acc1;
    arow[2 * NN] = W + acc2;
    arow[3 * NN] = W + acc3;
}

// ---------------------------------------------------------------------------
// Kernel SO: masked softmax (4 rows) + output GEMM with j split 2-way.
// grid = 256 blocks, 1024 threads.
// GEMM: thread t -> d = t&255, g = t>>8: jh = g&1 (j-half), rp = g>>1 (row pair)
// ---------------------------------------------------------------------------
__global__ __launch_bounds__(1024) void kSO(const int* __restrict__ mask,
                                            float* __restrict__ out,
                                            float* __restrict__ attn_out) {
    __shared__ float s_attn[4][NN];    // 8KB
    __shared__ float s_part[4][DM];    // 4KB: jh=1 partials

    const int t = threadIdx.x;
    const int blk = blockIdx.x;
    const int b = blk / (NN / 4);
    const int i0 = (blk % (NN / 4)) * 4;

    {
        const float4* src = (const float4*)(attn_out + (b * NN + i0) * NN);
        float4* dst = (float4*)&s_attn[0][0];
        for (int e = t; e < 4 * NN / 4; e += 1024) dst[e] = src[e];
    }
    __syncthreads();

    const int wid = t >> 5, lane = t & 31;
    if (wid < 4) {
        const int i = i0 + wid;
        const int4* m4 = (const int4*)(mask + (b * NN + i) * NN);
        float4* s4 = (float4*)&s_attn[wid][0];
        int4 mv[4];
        float4 sv[4];
#pragma unroll
        for (int k = 0; k < 4; k++) {
            mv[k] = m4[lane + 32 * k];
            sv[k] = s4[lane + 32 * k];
        }
        float mx = -INFINITY;
#pragma unroll
        for (int k = 0; k < 4; k++) {
            if (mv[k].x) mx = fmaxf(mx, sv[k].x);
            if (mv[k].y) mx = fmaxf(mx, sv[k].y);
            if (mv[k].z) mx = fmaxf(mx, sv[k].z);
            if (mv[k].w) mx = fmaxf(mx, sv[k].w);
        }
#pragma unroll
        for (int o = 16; o; o >>= 1) mx = fmaxf(mx, __shfl_xor_sync(0xffffffffu, mx, o));
        float sum = 0.f;
#pragma unroll
        for (int k = 0; k < 4; k++) {
            sv[k].x = mv[k].x ? __expf(sv[k].x - mx) : 0.f;
            sv[k].y = mv[k].y ? __expf(sv[k].y - mx) : 0.f;
            sv[k].z = mv[k].z ? __expf(sv[k].z - mx) : 0.f;
            sv[k].w = mv[k].w ? __expf(sv[k].w - mx) : 0.f;
            sum += sv[k].x + sv[k].y + sv[k].z + sv[k].w;
        }
#pragma unroll
        for (int o = 16; o; o >>= 1) sum += __shfl_xor_sync(0xffffffffu, sum, o);
        const float inv = (sum > 0.f) ? 1.f / sum : 0.f;
        float4* arow4 = (float4*)(attn_out + (b * NN + i) * NN);
#pragma unroll
        for (int k = 0; k < 4; k++) {
            sv[k].x *= inv; sv[k].y *= inv; sv[k].z *= inv; sv[k].w *= inv;
            s4[lane + 32 * k] = sv[k];
            arow4[lane + 32 * k] = sv[k];
        }
    }
    __syncthreads();

    // output GEMM, j split 2-way
    const int d  = t & (DM - 1);
    const int g  = t >> 8;          // 0..3
    const int jh = g & 1;           // j-half
    const int rp = g >> 1;          // row pair: rows {2rp, 2rp+1}
    float o0 = 0.f, o1 = 0.f;
    const float* hb = g_h + b * NN * DM + d;
    const float4* pA = (const float4*)&s_attn[2 * rp][0];
    const float4* pB = (const float4*)&s_attn[2 * rp + 1][0];
    const int j4b = jh * (NN / 8);  // 64 float4-groups per half
#pragma unroll 4
    for (int j4 = j4b; j4 < j4b + NN / 8; j4++) {
        float4 a = pA[j4];          // broadcast LDS.128
        float4 c = pB[j4];
        float h0 = hb[(4 * j4 + 0) * DM];
        float h1 = hb[(4 * j4 + 1) * DM];
        float h2 = hb[(4 * j4 + 2) * DM];
        float h3 = hb[(4 * j4 + 3) * DM];
        o0 += a.x * h0 + a.y * h1 + a.z * h2 + a.w * h3;
        o1 += c.x * h0 + c.y * h1 + c.z * h2 + c.w * h3;
    }
    if (jh) {
        s_part[2 * rp][d] = o0;
        s_part[2 * rp + 1][d] = o1;
    }
    __syncthreads();
    if (!jh) {
        o0 += s_part[2 * rp][d];
        o1 += s_part[2 * rp + 1][d];
        out[(b * NN + i0 + 2 * rp + 0) * DM + d] = o0;
        out[(b * NN + i0 + 2 * rp + 1) * DM + d] = o1;
    }
}

// ---------------------------------------------------------------------------
extern "C" void kernel_launch(void* const* d_in, const int* in_sizes, int n_in,
                              void* d_out, int out_size) {
    const float* x    = (const float*)d_in[0];  // [2,512,512]
    const float* pos  = (const float*)d_in[1];  // [2,512,4]
    const int*   mask = (const int*)  d_in[2];  // [2,512,512]
    const float* Wx   = (const float*)d_in[3];  // [512,256]
    const float* bx   = (const float*)d_in[4];  // [256]
    const float* Wp   = (const float*)d_in[5];  // [4,256]
    const float* bp   = (const float*)d_in[6];  // [256]
    const float* w    = (const float*)d_in[7];  // [256]

    float* out      = (float*)d_out;            // [2,512,256]
    float* attn_out = out + BB * NN * DM;       // [2,512,512]

    kA<<<BB * NN / 4, 1024>>>(x, pos, Wx, bx, Wp, bp);
    kScore<<<(BB * NN / 4) * 2, 256>>>(w, attn_out);
    kSO<<<BB * NN / 4, 1024>>>(mask, out, attn_out);
}

// round 10
// speedup vs baseline: 1.1642x; 1.0427x over previous
#include <cuda_runtime.h>
#include <math.h>

#define BB 2
#define NN 512
#define DIN 512
#define DM 256
#define C2LOG2E 2.885390081777927f   // 2*log2(e)

// scratch (static device globals — no allocation)
__device__ float g_h[BB * NN * DM];    // h[b][n][d] = tanh(x@Wx+bx)
__device__ float g_p[BB * NN * DM];    // P row-major: exp2(c*(u+bp))
__device__ float g_qt[BB * DM * NN];   // Q transposed: exp2(-c*u)[b][d][n]

__device__ __forceinline__ float ex2_fast(float x) {
    float y; asm("ex2.approx.f32 %0, %1;" : "=f"(y) : "f"(x)); return y;
}
__device__ __forceinline__ float rcp_fast(float x) {
    float y; asm("rcp.approx.f32 %0, %1;" : "=f"(y) : "f"(x)); return y;
}

// ---------------------------------------------------------------------------
// Kernel A (R9 best): h = tanh(x @ Wx + bx), P/Q projections.
// 4 rows/block, K split 4-way. grid 256 x 1024 threads.
// ---------------------------------------------------------------------------
__global__ __launch_bounds__(1024) void kA(const float* __restrict__ x,
                                           const float* __restrict__ pos,
                                           const float* __restrict__ Wx,
                                           const float* __restrict__ bx,
                                           const float* __restrict__ Wp,
                                           const float* __restrict__ bp) {
    __shared__ float s_x[DIN][4];        // 8KB
    __shared__ float s_part[3][4][DM];   // 12KB
    const int t = threadIdx.x;
    const int row0 = blockIdx.x * 4;
    const int c  = t & (DM - 1);
    const int kq = t >> 8;

    for (int e = t; e < DIN * 4; e += 1024) {
        int r = e >> 9, cc = e & (DIN - 1);
        s_x[cc][r] = x[(row0 + r) * DIN + cc];
    }
    __syncthreads();

    float a0 = 0.f, a1 = 0.f, a2 = 0.f, a3 = 0.f;
    const int kb = kq << 7;
#pragma unroll 8
    for (int k = 0; k < 128; k++) {
        float wv = Wx[(kb + k) * DM + c];
        float4 xv = *(const float4*)&s_x[kb + k][0];
        a0 += xv.x * wv; a1 += xv.y * wv;
        a2 += xv.z * wv; a3 += xv.w * wv;
    }
    if (kq) {
        s_part[kq - 1][0][c] = a0; s_part[kq - 1][1][c] = a1;
        s_part[kq - 1][2][c] = a2; s_part[kq - 1][3][c] = a3;
    }
    __syncthreads();
    if (kq == 0) {
        const float bias = bx[c];
        a0 += bias + s_part[0][0][c] + s_part[1][0][c] + s_part[2][0][c];
        a1 += bias + s_part[0][1][c] + s_part[1][1][c] + s_part[2][1][c];
        a2 += bias + s_part[0][2][c] + s_part[1][2][c] + s_part[2][2][c];
        a3 += bias + s_part[0][3][c] + s_part[1][3][c] + s_part[2][3][c];
        g_h[(row0 + 0) * DM + c] = tanhf(a0);
        g_h[(row0 + 1) * DM + c] = tanhf(a1);
        g_h[(row0 + 2) * DM + c] = tanhf(a2);
        g_h[(row0 + 3) * DM + c] = tanhf(a3);

        const int b = row0 / NN;
        const int n0 = row0 % NN;
        const float w0 = Wp[0 * DM + c], w1 = Wp[1 * DM + c];
        const float w2 = Wp[2 * DM + c], w3 = Wp[3 * DM + c];
        const float bpv = bp[c];
#pragma unroll
        for (int r = 0; r < 4; r++) {
            const float* p = pos + (row0 + r) * 4;
            float u = p[0] * w0 + p[1] * w1 + p[2] * w2 + p[3] * w3;
            g_p[(row0 + r) * DM + c] = ex2_fast(C2LOG2E * (u + bpv));
            g_qt[(b * DM + c) * NN + n0 + r] = ex2_fast(-C2LOG2E * u);
        }
    }
}

// ---------------------------------------------------------------------------
// Kernel Score: 4 query rows x 256 j's per block, d-reduction split 2-way.
// grid = 512 blocks, 512 threads (tj = t&255 -> j, dh = t>>8 -> d-half).
// score = W - 2*sum_d w_d/(1+P_i[d]*Q_j[d])
// ---------------------------------------------------------------------------
__global__ __launch_bounds__(512) void kScore(const float* __restrict__ w,
                                              float* __restrict__ attn_out) {
    __shared__ float s_pi[DM][4];      // 4KB
    __shared__ float s_wn[DM];         // 1KB
    __shared__ float s_part[4][256];   // 4KB: dh=1 partials
    __shared__ float s_W;

    const int t  = threadIdx.x;
    const int tj = t & 255;
    const int dh = t >> 8;             // d-half: 0 or 1
    const int jt = blockIdx.x & 1;
    const int it = blockIdx.x >> 1;
    const int b  = it / (NN / 4);
    const int i0 = (it % (NN / 4)) * 4;
    const int j  = jt * 256 + tj;

    if (t < DM) s_wn[t] = -2.0f * w[t];
    if (t < 32) {
        float s = 0.f;
#pragma unroll
        for (int k = 0; k < 8; k++) s += w[t + 32 * k];
#pragma unroll
        for (int o = 16; o; o >>= 1) s += __shfl_xor_sync(0xffffffffu, s, o);
        if (t == 0) s_W = s;
    }
    {
        const float* prow = g_p + (b * NN + i0) * DM;
        for (int e = t; e < 4 * DM; e += 512) {
            int r = e >> 8, d = e & (DM - 1);
            s_pi[d][r] = prow[r * DM + d];
        }
    }
    __syncthreads();

    float acc0 = 0.f, acc1 = 0.f, acc2 = 0.f, acc3 = 0.f;
    const float* qp = g_qt + b * DM * NN + j;
    const int db = dh << 7;            // 0 or 128
    float qbuf[4];
#pragma unroll
    for (int p = 0; p < 4; p++) qbuf[p] = qp[(db + p) * NN];

    for (int d0 = db; d0 < db + 128; d0 += 4) {
        float qc[4];
#pragma unroll
        for (int p = 0; p < 4; p++) qc[p] = qbuf[p];
        if (d0 + 4 < db + 128) {
#pragma unroll
            for (int p = 0; p < 4; p++) qbuf[p] = qp[(d0 + 4 + p) * NN];
        }
#pragma unroll
        for (int dd = 0; dd < 4; dd++) {
            const int d = d0 + dd;
            const float wn = s_wn[d];
            const float4 pi = *(const float4*)&s_pi[d][0];   // broadcast LDS.128
            const float qj = qc[dd];
            float de0 = fmaf(pi.x, qj, 1.0f);
            float de1 = fmaf(pi.y, qj, 1.0f);
            float de2 = fmaf(pi.z, qj, 1.0f);
            float de3 = fmaf(pi.w, qj, 1.0f);
            float r01 = rcp_fast(de0 * de1);
            float r23 = rcp_fast(de2 * de3);
            float w01 = wn * r01;
            float w23 = wn * r23;
            acc0 += w01 * de1;
            acc1 += w01 * de0;
            acc2 += w23 * de3;
            acc3 += w23 * de2;
        }
    }
    if (dh) {
        s_part[0][tj] = acc0; s_part[1][tj] = acc1;
        s_part[2][tj] = acc2; s_part[3][tj] = acc3;
    }
    __syncthreads();
    if (!dh) {
        const float W = s_W;
        float* arow = attn_out + (b * NN + i0) * NN + j;
        arow[0 * NN] = W + acc0 + s_part[0][tj];
        arow[1 * NN] = W + acc1 + s_part[1][tj];
        arow[2 * NN] = W + acc2 + s_part[2][tj];
        arow[3 * NN] = W + acc3 + s_part[3][tj];
    }
}

// ---------------------------------------------------------------------------
// Kernel SO (R9 best): masked softmax (4 rows) + output GEMM, j split 2-way.
// grid = 256 blocks, 1024 threads.
// ---------------------------------------------------------------------------
__global__ __launch_bounds__(1024) void kSO(const int* __restrict__ mask,
                                            float* __restrict__ out,
                                            float* __restrict__ attn_out) {
    __shared__ float s_attn[4][NN];    // 8KB
    __shared__ float s_part[4][DM];    // 4KB

    const int t = threadIdx.x;
    const int blk = blockIdx.x;
    const int b = blk / (NN / 4);
    const int i0 = (blk % (NN / 4)) * 4;

    {
        const float4* src = (const float4*)(attn_out + (b * NN + i0) * NN);
        float4* dst = (float4*)&s_attn[0][0];
        for (int e = t; e < 4 * NN / 4; e += 1024) dst[e] = src[e];
    }
    __syncthreads();

    const int wid = t >> 5, lane = t & 31;
    if (wid < 4) {
        const int i = i0 + wid;
        const int4* m4 = (const int4*)(mask + (b * NN + i) * NN);
        float4* s4 = (float4*)&s_attn[wid][0];
        int4 mv[4];
        float4 sv[4];
#pragma unroll
        for (int k = 0; k < 4; k++) {
            mv[k] = m4[lane + 32 * k];
            sv[k] = s4[lane + 32 * k];
        }
        float mx = -INFINITY;
#pragma unroll
        for (int k = 0; k < 4; k++) {
            if (mv[k].x) mx = fmaxf(mx, sv[k].x);
            if (mv[k].y) mx = fmaxf(mx, sv[k].y);
            if (mv[k].z) mx = fmaxf(mx, sv[k].z);
            if (mv[k].w) mx = fmaxf(mx, sv[k].w);
        }
#pragma unroll
        for (int o = 16; o; o >>= 1) mx = fmaxf(mx, __shfl_xor_sync(0xffffffffu, mx, o));
        float sum = 0.f;
#pragma unroll
        for (int k = 0; k < 4; k++) {
            sv[k].x = mv[k].x ? __expf(sv[k].x - mx) : 0.f;
            sv[k].y = mv[k].y ? __expf(sv[k].y - mx) : 0.f;
            sv[k].z = mv[k].z ? __expf(sv[k].z - mx) : 0.f;
            sv[k].w = mv[k].w ? __expf(sv[k].w - mx) : 0.f;
            sum += sv[k].x + sv[k].y + sv[k].z + sv[k].w;
        }
#pragma unroll
        for (int o = 16; o; o >>= 1) sum += __shfl_xor_sync(0xffffffffu, sum, o);
        const float inv = (sum > 0.f) ? 1.f / sum : 0.f;
        float4* arow4 = (float4*)(attn_out + (b * NN + i) * NN);
#pragma unroll
        for (int k = 0; k < 4; k++) {
            sv[k].x *= inv; sv[k].y *= inv; sv[k].z *= inv; sv[k].w *= inv;
            s4[lane + 32 * k] = sv[k];
            arow4[lane + 32 * k] = sv[k];
        }
    }
    __syncthreads();

    const int d  = t & (DM - 1);
    const int g  = t >> 8;
    const int jh = g & 1;
    const int rp = g >> 1;
    float o0 = 0.f, o1 = 0.f;
    const float* hb = g_h + b * NN * DM + d;
    const float4* pA = (const float4*)&s_attn[2 * rp][0];
    const float4* pB = (const float4*)&s_attn[2 * rp + 1][0];
    const int j4b = jh * (NN / 8);
#pragma unroll 4
    for (int j4 = j4b; j4 < j4b + NN / 8; j4++) {
        float4 a = pA[j4];
        float4 c = pB[j4];
        float h0 = hb[(4 * j4 + 0) * DM];
        float h1 = hb[(4 * j4 + 1) * DM];
        float h2 = hb[(4 * j4 + 2) * DM];
        float h3 = hb[(4 * j4 + 3) * DM];
        o0 += a.x * h0 + a.y * h1 + a.z * h2 + a.w * h3;
        o1 += c.x * h0 + c.y * h1 + c.z * h2 + c.w * h3;
    }
    if (jh) {
        s_part[2 * rp][d] = o0;
        s_part[2 * rp + 1][d] = o1;
    }
    __syncthreads();
    if (!jh) {
        o0 += s_part[2 * rp][d];
        o1 += s_part[2 * rp + 1][d];
        out[(b * NN + i0 + 2 * rp + 0) * DM + d] = o0;
        out[(b * NN + i0 + 2 * rp + 1) * DM + d] = o1;
    }
}

// ---------------------------------------------------------------------------
extern "C" void kernel_launch(void* const* d_in, const int* in_sizes, int n_in,
                              void* d_out, int out_size) {
    const float* x    = (const float*)d_in[0];  // [2,512,512]
    const float* pos  = (const float*)d_in[1];  // [2,512,4]
    const int*   mask = (const int*)  d_in[2];  // [2,512,512]
    const float* Wx   = (const float*)d_in[3];  // [512,256]
    const float* bx   = (const float*)d_in[4];  // [256]
    const float* Wp   = (const float*)d_in[5];  // [4,256]
    const float* bp   = (const float*)d_in[6];  // [256]
    const float* w    = (const float*)d_in[7];  // [256]

    float* out      = (float*)d_out;            // [2,512,256]
    float* attn_out = out + BB * NN * DM;       // [2,512,512]

    kA<<<BB * NN / 4, 1024>>>(x, pos, Wx, bx, Wp, bp);
    kScore<<<(BB * NN / 4) * 2, 512>>>(w, attn_out);
    kSO<<<BB * NN / 4, 1024>>>(mask, out, attn_out);
}

// round 11
// speedup vs baseline: 1.2831x; 1.1021x over previous
#include <cuda_runtime.h>
#include <math.h>

#define BB 2
#define NN 512
#define DIN 512
#define DM 256
#define C2LOG2E 2.885390081777927f   // 2*log2(e)

// scratch (static device globals — no allocation)
__device__ float g_h[BB * NN * DM];    // h[b][n][d] = tanh(x@Wx+bx)
__device__ float g_p[BB * NN * DM];    // P row-major: exp2(c*(u+bp))
__device__ float g_qt[BB * DM * NN];   // Q transposed: exp2(-c*u)[b][d][n]

__device__ __forceinline__ float ex2_fast(float x) {
    float y; asm("ex2.approx.f32 %0, %1;" : "=f"(y) : "f"(x)); return y;
}
__device__ __forceinline__ float rcp_fast(float x) {
    float y; asm("rcp.approx.f32 %0, %1;" : "=f"(y) : "f"(x)); return y;
}

// ---------------------------------------------------------------------------
// Kernel A: h = tanh(x @ Wx + bx), P/Q projections.
// 4 rows/block. Thread owns 2 columns (float2 Wx loads), K split 8-way
// (chain 64). grid 256 x 1024 threads. Partials reduced via smem tree.
// ---------------------------------------------------------------------------
__global__ __launch_bounds__(1024) void kA(const float* __restrict__ x,
                                           const float* __restrict__ pos,
                                           const float* __restrict__ Wx,
                                           const float* __restrict__ bx,
                                           const float* __restrict__ Wp,
                                           const float* __restrict__ bp) {
    __shared__ float s_x[DIN][4];          // 8KB
    __shared__ float s_part[8][4][DM];     // 32KB
    const int t = threadIdx.x;
    const int row0 = blockIdx.x * 4;
    const int c2 = (t & 127) * 2;          // columns c2, c2+1
    const int kq = t >> 7;                 // K-eighth: 0..7
    const int b = row0 / NN;
    const int n0 = row0 % NN;

    // pos projection first (independent, overlaps the x-tile load)
    if (t < DM) {
        const float w0 = Wp[0 * DM + t], w1 = Wp[1 * DM + t];
        const float w2 = Wp[2 * DM + t], w3 = Wp[3 * DM + t];
        const float bpv = bp[t];
#pragma unroll
        for (int r = 0; r < 4; r++) {
            const float* p = pos + (row0 + r) * 4;
            float u = p[0] * w0 + p[1] * w1 + p[2] * w2 + p[3] * w3;
            g_p[(row0 + r) * DM + t] = ex2_fast(C2LOG2E * (u + bpv));
            g_qt[(b * DM + t) * NN + n0 + r] = ex2_fast(-C2LOG2E * u);
        }
    }

    for (int e = t; e < DIN * 4; e += 1024) {
        int r = e >> 9, cc = e & (DIN - 1);
        s_x[cc][r] = x[(row0 + r) * DIN + cc];
    }
    __syncthreads();

    float a00 = 0.f, a01 = 0.f, a10 = 0.f, a11 = 0.f;
    float a20 = 0.f, a21 = 0.f, a30 = 0.f, a31 = 0.f;
    const int kb = kq << 6;                // 64 k per group
#pragma unroll 8
    for (int k = 0; k < 64; k++) {
        float2 wv = *(const float2*)&Wx[(kb + k) * DM + c2];  // LDG.64 coalesced
        float4 xv = *(const float4*)&s_x[kb + k][0];          // broadcast LDS.128
        a00 += xv.x * wv.x; a01 += xv.x * wv.y;
        a10 += xv.y * wv.x; a11 += xv.y * wv.y;
        a20 += xv.z * wv.x; a21 += xv.z * wv.y;
        a30 += xv.w * wv.x; a31 += xv.w * wv.y;
    }
    s_part[kq][0][c2] = a00; s_part[kq][0][c2 + 1] = a01;
    s_part[kq][1][c2] = a10; s_part[kq][1][c2 + 1] = a11;
    s_part[kq][2][c2] = a20; s_part[kq][2][c2 + 1] = a21;
    s_part[kq][3][c2] = a30; s_part[kq][3][c2 + 1] = a31;
    __syncthreads();

    // reduce: thread t -> (row = t>>8, col = t&255)
    {
        const int r = t >> 8;
        const int c = t & (DM - 1);
        float s = bx[c];
#pragma unroll
        for (int g = 0; g < 8; g++) s += s_part[g][r][c];
        g_h[(row0 + r) * DM + c] = tanhf(s);
    }
}

// ---------------------------------------------------------------------------
// Kernel Score (R10 best, unchanged): 4 rows x 256 j per block, d split 2-way.
// grid = 512 blocks, 512 threads.
// ---------------------------------------------------------------------------
__global__ __launch_bounds__(512) void kScore(const float* __restrict__ w,
                                              float* __restrict__ attn_out) {
    __shared__ float s_pi[DM][4];
    __shared__ float s_wn[DM];
    __shared__ float s_part[4][256];
    __shared__ float s_W;

    const int t  = threadIdx.x;
    const int tj = t & 255;
    const int dh = t >> 8;
    const int jt = blockIdx.x & 1;
    const int it = blockIdx.x >> 1;
    const int b  = it / (NN / 4);
    const int i0 = (it % (NN / 4)) * 4;
    const int j  = jt * 256 + tj;

    if (t < DM) s_wn[t] = -2.0f * w[t];
    if (t < 32) {
        float s = 0.f;
#pragma unroll
        for (int k = 0; k < 8; k++) s += w[t + 32 * k];
#pragma unroll
        for (int o = 16; o; o >>= 1) s += __shfl_xor_sync(0xffffffffu, s, o);
        if (t == 0) s_W = s;
    }
    {
        const float* prow = g_p + (b * NN + i0) * DM;
        for (int e = t; e < 4 * DM; e += 512) {
            int r = e >> 8, d = e & (DM - 1);
            s_pi[d][r] = prow[r * DM + d];
        }
    }
    __syncthreads();

    float acc0 = 0.f, acc1 = 0.f, acc2 = 0.f, acc3 = 0.f;
    const float* qp = g_qt + b * DM * NN + j;
    const int db = dh << 7;
    float qbuf[4];
#pragma unroll
    for (int p = 0; p < 4; p++) qbuf[p] = qp[(db + p) * NN];

    for (int d0 = db; d0 < db + 128; d0 += 4) {
        float qc[4];
#pragma unroll
        for (int p = 0; p < 4; p++) qc[p] = qbuf[p];
        if (d0 + 4 < db + 128) {
#pragma unroll
            for (int p = 0; p < 4; p++) qbuf[p] = qp[(d0 + 4 + p) * NN];
        }
#pragma unroll
        for (int dd = 0; dd < 4; dd++) {
            const int d = d0 + dd;
            const float wn = s_wn[d];
            const float4 pi = *(const float4*)&s_pi[d][0];
            const float qj = qc[dd];
            float de0 = fmaf(pi.x, qj, 1.0f);
            float de1 = fmaf(pi.y, qj, 1.0f);
            float de2 = fmaf(pi.z, qj, 1.0f);
            float de3 = fmaf(pi.w, qj, 1.0f);
            float r01 = rcp_fast(de0 * de1);
            float r23 = rcp_fast(de2 * de3);
            float w01 = wn * r01;
            float w23 = wn * r23;
            acc0 += w01 * de1;
            acc1 += w01 * de0;
            acc2 += w23 * de3;
            acc3 += w23 * de2;
        }
    }
    if (dh) {
        s_part[0][tj] = acc0; s_part[1][tj] = acc1;
        s_part[2][tj] = acc2; s_part[3][tj] = acc3;
    }
    __syncthreads();
    if (!dh) {
        const float W = s_W;
        float* arow = attn_out + (b * NN + i0) * NN + j;
        arow[0 * NN] = W + acc0 + s_part[0][tj];
        arow[1 * NN] = W + acc1 + s_part[1][tj];
        arow[2 * NN] = W + acc2 + s_part[2][tj];
        arow[3 * NN] = W + acc3 + s_part[3][tj];
    }
}

// ---------------------------------------------------------------------------
// Kernel SO: masked softmax (4 rows) + output GEMM with j split 4-way.
// grid = 256 blocks, 1024 threads. Thread t: d = t&255, g = t>>8 = j-quarter,
// accumulates all 4 rows over its 128 j's; smem tree reduce.
// ---------------------------------------------------------------------------
__global__ __launch_bounds__(1024) void kSO(const int* __restrict__ mask,
                                            float* __restrict__ out,
                                            float* __restrict__ attn_out) {
    __shared__ float s_attn[4][NN];      // 8KB
    __shared__ float s_part[4][4][DM];   // 16KB: [group][row][d]

    const int t = threadIdx.x;
    const int blk = blockIdx.x;
    const int b = blk / (NN / 4);
    const int i0 = (blk % (NN / 4)) * 4;

    {
        const float4* src = (const float4*)(attn_out + (b * NN + i0) * NN);
        float4* dst = (float4*)&s_attn[0][0];
        for (int e = t; e < 4 * NN / 4; e += 1024) dst[e] = src[e];
    }
    __syncthreads();

    const int wid = t >> 5, lane = t & 31;
    if (wid < 4) {
        const int i = i0 + wid;
        const int4* m4 = (const int4*)(mask + (b * NN + i) * NN);
        float4* s4 = (float4*)&s_attn[wid][0];
        int4 mv[4];
        float4 sv[4];
#pragma unroll
        for (int k = 0; k < 4; k++) {
            mv[k] = m4[lane + 32 * k];
            sv[k] = s4[lane + 32 * k];
        }
        float mx = -INFINITY;
#pragma unroll
        for (int k = 0; k < 4; k++) {
            if (mv[k].x) mx = fmaxf(mx, sv[k].x);
            if (mv[k].y) mx = fmaxf(mx, sv[k].y);
            if (mv[k].z) mx = fmaxf(mx, sv[k].z);
            if (mv[k].w) mx = fmaxf(mx, sv[k].w);
        }
#pragma unroll
        for (int o = 16; o; o >>= 1) mx = fmaxf(mx, __shfl_xor_sync(0xffffffffu, mx, o));
        float sum = 0.f;
#pragma unroll
        for (int k = 0; k < 4; k++) {
            sv[k].x = mv[k].x ? __expf(sv[k].x - mx) : 0.f;
            sv[k].y = mv[k].y ? __expf(sv[k].y - mx) : 0.f;
            sv[k].z = mv[k].z ? __expf(sv[k].z - mx) : 0.f;
            sv[k].w = mv[k].w ? __expf(sv[k].w - mx) : 0.f;
            sum += sv[k].x + sv[k].y + sv[k].z + sv[k].w;
        }
#pragma unroll
        for (int o = 16; o; o >>= 1) sum += __shfl_xor_sync(0xffffffffu, sum, o);
        const float inv = (sum > 0.f) ? 1.f / sum : 0.f;
        float4* arow4 = (float4*)(attn_out + (b * NN + i) * NN);
#pragma unroll
        for (int k = 0; k < 4; k++) {
            sv[k].x *= inv; sv[k].y *= inv; sv[k].z *= inv; sv[k].w *= inv;
            s4[lane + 32 * k] = sv[k];
            arow4[lane + 32 * k] = sv[k];
        }
    }
    __syncthreads();

    // output GEMM: thread t -> d, j-quarter g; all 4 rows per thread.
    {
        const int d = t & (DM - 1);
        const int g = t >> 8;               // 0..3
        float o0 = 0.f, o1 = 0.f, o2 = 0.f, o3 = 0.f;
        const float* hb = g_h + b * NN * DM + d;
        const float4* p0 = (const float4*)&s_attn[0][0];
        const float4* p1 = (const float4*)&s_attn[1][0];
        const float4* p2 = (const float4*)&s_attn[2][0];
        const float4* p3 = (const float4*)&s_attn[3][0];
        const int j4b = g * (NN / 16);      // 32 float4-groups per quarter
#pragma unroll 4
        for (int j4 = j4b; j4 < j4b + NN / 16; j4++) {
            float h0 = hb[(4 * j4 + 0) * DM];
            float h1 = hb[(4 * j4 + 1) * DM];
            float h2 = hb[(4 * j4 + 2) * DM];
            float h3 = hb[(4 * j4 + 3) * DM];
            float4 a0 = p0[j4];             // broadcast LDS.128
            float4 a1 = p1[j4];
            float4 a2 = p2[j4];
            float4 a3 = p3[j4];
            o0 += a0.x * h0 + a0.y * h1 + a0.z * h2 + a0.w * h3;
            o1 += a1.x * h0 + a1.y * h1 + a1.z * h2 + a1.w * h3;
            o2 += a2.x * h0 + a2.y * h1 + a2.z * h2 + a2.w * h3;
            o3 += a3.x * h0 + a3.y * h1 + a3.z * h2 + a3.w * h3;
        }
        s_part[g][0][d] = o0;
        s_part[g][1][d] = o1;
        s_part[g][2][d] = o2;
        s_part[g][3][d] = o3;
    }
    __syncthreads();

    // reduce: thread t -> (row = t>>8, d = t&255)
    {
        const int r = t >> 8;
        const int d = t & (DM - 1);
        float s = s_part[0][r][d] + s_part[1][r][d]
                + s_part[2][r][d] + s_part[3][r][d];
        out[(b * NN + i0 + r) * DM + d] = s;
    }
}

// ---------------------------------------------------------------------------
extern "C" void kernel_launch(void* const* d_in, const int* in_sizes, int n_in,
                              void* d_out, int out_size) {
    const float* x    = (const float*)d_in[0];  // [2,512,512]
    const float* pos  = (const float*)d_in[1];  // [2,512,4]
    const int*   mask = (const int*)  d_in[2];  // [2,512,512]
    const float* Wx   = (const float*)d_in[3];  // [512,256]
    const float* bx   = (const float*)d_in[4];  // [256]
    const float* Wp   = (const float*)d_in[5];  // [4,256]
    const float* bp   = (const float*)d_in[6];  // [256]
    const float* w    = (const float*)d_in[7];  // [256]

    float* out      = (float*)d_out;            // [2,512,256]
    float* attn_out = out + BB * NN * DM;       // [2,512,512]

    kA<<<BB * NN / 4, 1024>>>(x, pos, Wx, bx, Wp, bp);
    kScore<<<(BB * NN / 4) * 2, 512>>>(w, attn_out);
    kSO<<<BB * NN / 4, 1024>>>(mask, out, attn_out);
}

// round 12
// speedup vs baseline: 1.3658x; 1.0645x over previous
#include <cuda_runtime.h>
#include <math.h>

#define BB 2
#define NN 512
#define DIN 512
#define DM 256
#define C2LOG2E 2.885390081777927f   // 2*log2(e)

// scratch (static device globals — no allocation)
__device__ float g_h[BB * NN * DM];    // h[b][n][d] = tanh(x@Wx+bx)
__device__ float g_p[BB * NN * DM];    // P row-major: exp2(c*(u+bp))
__device__ float g_qt[BB * DM * NN];   // Q transposed: exp2(-c*u)[b][d][n]

__device__ __forceinline__ float ex2_fast(float x) {
    float y; asm("ex2.approx.f32 %0, %1;" : "=f"(y) : "f"(x)); return y;
}
__device__ __forceinline__ float rcp_fast(float x) {
    float y; asm("rcp.approx.f32 %0, %1;" : "=f"(y) : "f"(x)); return y;
}

// ---------------------------------------------------------------------------
// Kernel A (R11 best): h = tanh(x @ Wx + bx), P/Q projections.
// 4 rows/block, thread owns 2 cols (float2 Wx), K split 8-way.
// grid 256 x 1024 threads.
// ---------------------------------------------------------------------------
__global__ __launch_bounds__(1024) void kA(const float* __restrict__ x,
                                           const float* __restrict__ pos,
                                           const float* __restrict__ Wx,
                                           const float* __restrict__ bx,
                                           const float* __restrict__ Wp,
                                           const float* __restrict__ bp) {
    __shared__ float s_x[DIN][4];          // 8KB
    __shared__ float s_part[8][4][DM];     // 32KB
    const int t = threadIdx.x;
    const int row0 = blockIdx.x * 4;
    const int c2 = (t & 127) * 2;
    const int kq = t >> 7;
    const int b = row0 / NN;
    const int n0 = row0 % NN;

    if (t < DM) {
        const float w0 = Wp[0 * DM + t], w1 = Wp[1 * DM + t];
        const float w2 = Wp[2 * DM + t], w3 = Wp[3 * DM + t];
        const float bpv = bp[t];
#pragma unroll
        for (int r = 0; r < 4; r++) {
            const float* p = pos + (row0 + r) * 4;
            float u = p[0] * w0 + p[1] * w1 + p[2] * w2 + p[3] * w3;
            g_p[(row0 + r) * DM + t] = ex2_fast(C2LOG2E * (u + bpv));
            g_qt[(b * DM + t) * NN + n0 + r] = ex2_fast(-C2LOG2E * u);
        }
    }

    for (int e = t; e < DIN * 4; e += 1024) {
        int r = e >> 9, cc = e & (DIN - 1);
        s_x[cc][r] = x[(row0 + r) * DIN + cc];
    }
    __syncthreads();

    float a00 = 0.f, a01 = 0.f, a10 = 0.f, a11 = 0.f;
    float a20 = 0.f, a21 = 0.f, a30 = 0.f, a31 = 0.f;
    const int kb = kq << 6;
#pragma unroll 8
    for (int k = 0; k < 64; k++) {
        float2 wv = *(const float2*)&Wx[(kb + k) * DM + c2];
        float4 xv = *(const float4*)&s_x[kb + k][0];
        a00 += xv.x * wv.x; a01 += xv.x * wv.y;
        a10 += xv.y * wv.x; a11 += xv.y * wv.y;
        a20 += xv.z * wv.x; a21 += xv.z * wv.y;
        a30 += xv.w * wv.x; a31 += xv.w * wv.y;
    }
    s_part[kq][0][c2] = a00; s_part[kq][0][c2 + 1] = a01;
    s_part[kq][1][c2] = a10; s_part[kq][1][c2 + 1] = a11;
    s_part[kq][2][c2] = a20; s_part[kq][2][c2 + 1] = a21;
    s_part[kq][3][c2] = a30; s_part[kq][3][c2 + 1] = a31;
    __syncthreads();

    {
        const int r = t >> 8;
        const int c = t & (DM - 1);
        float s = bx[c];
#pragma unroll
        for (int g = 0; g < 8; g++) s += s_part[g][r][c];
        g_h[(row0 + r) * DM + c] = tanhf(s);
    }
}

// ---------------------------------------------------------------------------
// Kernel Score: 4 rows x 256 j per block, d split 2-way, BATCHED-4 RCP.
// grid = 512 blocks, 512 threads.  One RCP serves all 4 rows per d:
//   tot = (de0*de1)*(de2*de3); r = rcp(tot);
//   inv01 = r*p23; inv23 = r*p01;  acc_k += (wn*inv)*de_sibling
// ---------------------------------------------------------------------------
__global__ __launch_bounds__(512) void kScore(const float* __restrict__ w,
                                              float* __restrict__ attn_out) {
    __shared__ float s_pi[DM][4];
    __shared__ float s_wn[DM];
    __shared__ float s_part[4][256];
    __shared__ float s_W;

    const int t  = threadIdx.x;
    const int tj = t & 255;
    const int dh = t >> 8;
    const int jt = blockIdx.x & 1;
    const int it = blockIdx.x >> 1;
    const int b  = it / (NN / 4);
    const int i0 = (it % (NN / 4)) * 4;
    const int j  = jt * 256 + tj;

    if (t < DM) s_wn[t] = -2.0f * w[t];
    if (t < 32) {
        float s = 0.f;
#pragma unroll
        for (int k = 0; k < 8; k++) s += w[t + 32 * k];
#pragma unroll
        for (int o = 16; o; o >>= 1) s += __shfl_xor_sync(0xffffffffu, s, o);
        if (t == 0) s_W = s;
    }
    {
        const float* prow = g_p + (b * NN + i0) * DM;
        for (int e = t; e < 4 * DM; e += 512) {
            int r = e >> 8, d = e & (DM - 1);
            s_pi[d][r] = prow[r * DM + d];
        }
    }
    __syncthreads();

    float acc0 = 0.f, acc1 = 0.f, acc2 = 0.f, acc3 = 0.f;
    const float* qp = g_qt + b * DM * NN + j;
    const int db = dh << 7;
    float qbuf[4];
#pragma unroll
    for (int p = 0; p < 4; p++) qbuf[p] = qp[(db + p) * NN];

    for (int d0 = db; d0 < db + 128; d0 += 4) {
        float qc[4];
#pragma unroll
        for (int p = 0; p < 4; p++) qc[p] = qbuf[p];
        if (d0 + 4 < db + 128) {
#pragma unroll
            for (int p = 0; p < 4; p++) qbuf[p] = qp[(d0 + 4 + p) * NN];
        }
#pragma unroll
        for (int dd = 0; dd < 4; dd++) {
            const int d = d0 + dd;
            const float wn = s_wn[d];
            const float4 pi = *(const float4*)&s_pi[d][0];   // broadcast LDS.128
            const float qj = qc[dd];
            float de0 = fmaf(pi.x, qj, 1.0f);
            float de1 = fmaf(pi.y, qj, 1.0f);
            float de2 = fmaf(pi.z, qj, 1.0f);
            float de3 = fmaf(pi.w, qj, 1.0f);
            float p01 = de0 * de1;
            float p23 = de2 * de3;
            float r = rcp_fast(p01 * p23);    // ONE rcp for 4 rows
            float i01 = r * p23;              // = 1/(de0*de1)
            float i23 = r * p01;              // = 1/(de2*de3)
            float w01 = wn * i01;
            float w23 = wn * i23;
            acc0 += w01 * de1;
            acc1 += w01 * de0;
            acc2 += w23 * de3;
            acc3 += w23 * de2;
        }
    }
    if (dh) {
        s_part[0][tj] = acc0; s_part[1][tj] = acc1;
        s_part[2][tj] = acc2; s_part[3][tj] = acc3;
    }
    __syncthreads();
    if (!dh) {
        const float W = s_W;
        float* arow = attn_out + (b * NN + i0) * NN + j;
        arow[0 * NN] = W + acc0 + s_part[0][tj];
        arow[1 * NN] = W + acc1 + s_part[1][tj];
        arow[2 * NN] = W + acc2 + s_part[2][tj];
        arow[3 * NN] = W + acc3 + s_part[3][tj];
    }
}

// ---------------------------------------------------------------------------
// Kernel SO (R11 best): masked softmax (4 rows) + output GEMM, j split 4-way.
// grid = 256 blocks, 1024 threads.
// ---------------------------------------------------------------------------
__global__ __launch_bounds__(1024) void kSO(const int* __restrict__ mask,
                                            float* __restrict__ out,
                                            float* __restrict__ attn_out) {
    __shared__ float s_attn[4][NN];      // 8KB
    __shared__ float s_part[4][4][DM];   // 16KB

    const int t = threadIdx.x;
    const int blk = blockIdx.x;
    const int b = blk / (NN / 4);
    const int i0 = (blk % (NN / 4)) * 4;

    {
        const float4* src = (const float4*)(attn_out + (b * NN + i0) * NN);
        float4* dst = (float4*)&s_attn[0][0];
        for (int e = t; e < 4 * NN / 4; e += 1024) dst[e] = src[e];
    }
    __syncthreads();

    const int wid = t >> 5, lane = t & 31;
    if (wid < 4) {
        const int i = i0 + wid;
        const int4* m4 = (const int4*)(mask + (b * NN + i) * NN);
        float4* s4 = (float4*)&s_attn[wid][0];
        int4 mv[4];
        float4 sv[4];
#pragma unroll
        for (int k = 0; k < 4; k++) {
            mv[k] = m4[lane + 32 * k];
            sv[k] = s4[lane + 32 * k];
        }
        float mx = -INFINITY;
#pragma unroll
        for (int k = 0; k < 4; k++) {
            if (mv[k].x) mx = fmaxf(mx, sv[k].x);
            if (mv[k].y) mx = fmaxf(mx, sv[k].y);
            if (mv[k].z) mx = fmaxf(mx, sv[k].z);
            if (mv[k].w) mx = fmaxf(mx, sv[k].w);
        }
#pragma unroll
        for (int o = 16; o; o >>= 1) mx = fmaxf(mx, __shfl_xor_sync(0xffffffffu, mx, o));
        float sum = 0.f;
#pragma unroll
        for (int k = 0; k < 4; k++) {
            sv[k].x = mv[k].x ? __expf(sv[k].x - mx) : 0.f;
            sv[k].y = mv[k].y ? __expf(sv[k].y - mx) : 0.f;
            sv[k].z = mv[k].z ? __expf(sv[k].z - mx) : 0.f;
            sv[k].w = mv[k].w ? __expf(sv[k].w - mx) : 0.f;
            sum += sv[k].x + sv[k].y + sv[k].z + sv[k].w;
        }
#pragma unroll
        for (int o = 16; o; o >>= 1) sum += __shfl_xor_sync(0xffffffffu, sum, o);
        const float inv = (sum > 0.f) ? 1.f / sum : 0.f;
        float4* arow4 = (float4*)(attn_out + (b * NN + i) * NN);
#pragma unroll
        for (int k = 0; k < 4; k++) {
            sv[k].x *= inv; sv[k].y *= inv; sv[k].z *= inv; sv[k].w *= inv;
            s4[lane + 32 * k] = sv[k];
            arow4[lane + 32 * k] = sv[k];
        }
    }
    __syncthreads();

    {
        const int d = t & (DM - 1);
        const int g = t >> 8;
        float o0 = 0.f, o1 = 0.f, o2 = 0.f, o3 = 0.f;
        const float* hb = g_h + b * NN * DM + d;
        const float4* p0 = (const float4*)&s_attn[0][0];
        const float4* p1 = (const float4*)&s_attn[1][0];
        const float4* p2 = (const float4*)&s_attn[2][0];
        const float4* p3 = (const float4*)&s_attn[3][0];
        const int j4b = g * (NN / 16);
#pragma unroll 4
        for (int j4 = j4b; j4 < j4b + NN / 16; j4++) {
            float h0 = hb[(4 * j4 + 0) * DM];
            float h1 = hb[(4 * j4 + 1) * DM];
            float h2 = hb[(4 * j4 + 2) * DM];
            float h3 = hb[(4 * j4 + 3) * DM];
            float4 a0 = p0[j4];
            float4 a1 = p1[j4];
            float4 a2 = p2[j4];
            float4 a3 = p3[j4];
            o0 += a0.x * h0 + a0.y * h1 + a0.z * h2 + a0.w * h3;
            o1 += a1.x * h0 + a1.y * h1 + a1.z * h2 + a1.w * h3;
            o2 += a2.x * h0 + a2.y * h1 + a2.z * h2 + a2.w * h3;
            o3 += a3.x * h0 + a3.y * h1 + a3.z * h2 + a3.w * h3;
        }
        s_part[g][0][d] = o0;
        s_part[g][1][d] = o1;
        s_part[g][2][d] = o2;
        s_part[g][3][d] = o3;
    }
    __syncthreads();

    {
        const int r = t >> 8;
        const int d = t & (DM - 1);
        float s = s_part[0][r][d] + s_part[1][r][d]
                + s_part[2][r][d] + s_part[3][r][d];
        out[(b * NN + i0 + r) * DM + d] = s;
    }
}

// ---------------------------------------------------------------------------
extern "C" void kernel_launch(void* const* d_in, const int* in_sizes, int n_in,
                              void* d_out, int out_size) {
    const float* x    = (const float*)d_in[0];  // [2,512,512]
    const float* pos  = (const float*)d_in[1];  // [2,512,4]
    const int*   mask = (const int*)  d_in[2];  // [2,512,512]
    const float* Wx   = (const float*)d_in[3];  // [512,256]
    const float* bx   = (const float*)d_in[4];  // [256]
    const float* Wp   = (const float*)d_in[5];  // [4,256]
    const float* bp   = (const float*)d_in[6];  // [256]
    const float* w    = (const float*)d_in[7];  // [256]

    float* out      = (float*)d_out;            // [2,512,256]
    float* attn_out = out + BB * NN * DM;       // [2,512,512]

    kA<<<BB * NN / 4, 1024>>>(x, pos, Wx, bx, Wp, bp);
    kScore<<<(BB * NN / 4) * 2, 512>>>(w, attn_out);
    kSO<<<BB * NN / 4, 1024>>>(mask, out, attn_out);
}

// round 13
// speedup vs baseline: 1.4572x; 1.0669x over previous
#include <cuda_runtime.h>
#include <math.h>

#define BB 2
#define NN 512
#define DIN 512
#define DM 256
#define C2LOG2E 2.885390081777927f   // 2*log2(e)

// scratch (static device globals — no allocation)
__device__ float g_h[BB * NN * DM];    // h[b][n][d] = tanh(x@Wx+bx)
__device__ float g_p[BB * NN * DM];    // P row-major: exp2(c*(u+bp))
__device__ float g_qt[BB * DM * NN];   // Q transposed: exp2(-c*u)[b][d][n]

__device__ __forceinline__ float ex2_fast(float x) {
    float y; asm("ex2.approx.f32 %0, %1;" : "=f"(y) : "f"(x)); return y;
}
__device__ __forceinline__ float rcp_fast(float x) {
    float y; asm("rcp.approx.f32 %0, %1;" : "=f"(y) : "f"(x)); return y;
}

// ---------------------------------------------------------------------------
// Kernel A (R11/R12 best): h = tanh(x @ Wx + bx), P/Q projections.
// 4 rows/block, thread owns 2 cols (float2 Wx), K split 8-way.
// grid 256 x 1024 threads.
// ---------------------------------------------------------------------------
__global__ __launch_bounds__(1024) void kA(const float* __restrict__ x,
                                           const float* __restrict__ pos,
                                           const float* __restrict__ Wx,
                                           const float* __restrict__ bx,
                                           const float* __restrict__ Wp,
                                           const float* __restrict__ bp) {
    __shared__ float s_x[DIN][4];          // 8KB
    __shared__ float s_part[8][4][DM];     // 32KB
    const int t = threadIdx.x;
    const int row0 = blockIdx.x * 4;
    const int c2 = (t & 127) * 2;
    const int kq = t >> 7;
    const int b = row0 / NN;
    const int n0 = row0 % NN;

    if (t < DM) {
        const float w0 = Wp[0 * DM + t], w1 = Wp[1 * DM + t];
        const float w2 = Wp[2 * DM + t], w3 = Wp[3 * DM + t];
        const float bpv = bp[t];
#pragma unroll
        for (int r = 0; r < 4; r++) {
            const float* p = pos + (row0 + r) * 4;
            float u = p[0] * w0 + p[1] * w1 + p[2] * w2 + p[3] * w3;
            g_p[(row0 + r) * DM + t] = ex2_fast(C2LOG2E * (u + bpv));
            g_qt[(b * DM + t) * NN + n0 + r] = ex2_fast(-C2LOG2E * u);
        }
    }

    for (int e = t; e < DIN * 4; e += 1024) {
        int r = e >> 9, cc = e & (DIN - 1);
        s_x[cc][r] = x[(row0 + r) * DIN + cc];
    }
    __syncthreads();

    float a00 = 0.f, a01 = 0.f, a10 = 0.f, a11 = 0.f;
    float a20 = 0.f, a21 = 0.f, a30 = 0.f, a31 = 0.f;
    const int kb = kq << 6;
#pragma unroll 8
    for (int k = 0; k < 64; k++) {
        float2 wv = *(const float2*)&Wx[(kb + k) * DM + c2];
        float4 xv = *(const float4*)&s_x[kb + k][0];
        a00 += xv.x * wv.x; a01 += xv.x * wv.y;
        a10 += xv.y * wv.x; a11 += xv.y * wv.y;
        a20 += xv.z * wv.x; a21 += xv.z * wv.y;
        a30 += xv.w * wv.x; a31 += xv.w * wv.y;
    }
    s_part[kq][0][c2] = a00; s_part[kq][0][c2 + 1] = a01;
    s_part[kq][1][c2] = a10; s_part[kq][1][c2 + 1] = a11;
    s_part[kq][2][c2] = a20; s_part[kq][2][c2 + 1] = a21;
    s_part[kq][3][c2] = a30; s_part[kq][3][c2 + 1] = a31;
    __syncthreads();

    {
        const int r = t >> 8;
        const int c = t & (DM - 1);
        float s = bx[c];
#pragma unroll
        for (int g = 0; g < 8; g++) s += s_part[g][r][c];
        g_h[(row0 + r) * DM + c] = tanhf(s);
    }
}

// ---------------------------------------------------------------------------
// Kernel Score: 4 rows x 128 j per block, d split 4-way, batched-4 RCP.
// grid = (B*N/4)*4 = 1024 blocks, 512 threads (tj = t&127 -> j, dq = t>>7).
// Q traffic halves vs j-tile 256; serial d-chain = 64.
// ---------------------------------------------------------------------------
__global__ __launch_bounds__(512) void kScore(const float* __restrict__ w,
                                              float* __restrict__ attn_out) {
    __shared__ float s_pi[DM][4];       // 4KB
    __shared__ float s_wn[DM];          // 1KB
    __shared__ float s_part[3][4][128]; // 6KB: dq=1..3 partials
    __shared__ float s_W;

    const int t  = threadIdx.x;
    const int tj = t & 127;
    const int dq = t >> 7;              // d-quarter 0..3
    const int jt = blockIdx.x & 3;      // 4 j-tiles of 128
    const int it = blockIdx.x >> 2;     // row-quad index
    const int b  = it / (NN / 4);
    const int i0 = (it % (NN / 4)) * 4;
    const int j  = jt * 128 + tj;

    if (t < DM) s_wn[t] = -2.0f * w[t];
    if (t < 32) {
        float s = 0.f;
#pragma unroll
        for (int k = 0; k < 8; k++) s += w[t + 32 * k];
#pragma unroll
        for (int o = 16; o; o >>= 1) s += __shfl_xor_sync(0xffffffffu, s, o);
        if (t == 0) s_W = s;
    }
    {
        const float* prow = g_p + (b * NN + i0) * DM;
        for (int e = t; e < 4 * DM; e += 512) {
            int r = e >> 8, d = e & (DM - 1);
            s_pi[d][r] = prow[r * DM + d];
        }
    }
    __syncthreads();

    float acc0 = 0.f, acc1 = 0.f, acc2 = 0.f, acc3 = 0.f;
    const float* qp = g_qt + b * DM * NN + j;
    const int db = dq << 6;             // 64 d per quarter
    float qbuf[4];
#pragma unroll
    for (int p = 0; p < 4; p++) qbuf[p] = qp[(db + p) * NN];

    for (int d0 = db; d0 < db + 64; d0 += 4) {
        float qc[4];
#pragma unroll
        for (int p = 0; p < 4; p++) qc[p] = qbuf[p];
        if (d0 + 4 < db + 64) {
#pragma unroll
            for (int p = 0; p < 4; p++) qbuf[p] = qp[(d0 + 4 + p) * NN];
        }
#pragma unroll
        for (int dd = 0; dd < 4; dd++) {
            const int d = d0 + dd;
            const float wn = s_wn[d];
            const float4 pi = *(const float4*)&s_pi[d][0];   // broadcast LDS.128
            const float qj = qc[dd];
            float de0 = fmaf(pi.x, qj, 1.0f);
            float de1 = fmaf(pi.y, qj, 1.0f);
            float de2 = fmaf(pi.z, qj, 1.0f);
            float de3 = fmaf(pi.w, qj, 1.0f);
            float p01 = de0 * de1;
            float p23 = de2 * de3;
            float r = rcp_fast(p01 * p23);    // ONE rcp for 4 rows
            float i01 = r * p23;
            float i23 = r * p01;
            float w01 = wn * i01;
            float w23 = wn * i23;
            acc0 += w01 * de1;
            acc1 += w01 * de0;
            acc2 += w23 * de3;
            acc3 += w23 * de2;
        }
    }
    if (dq) {
        s_part[dq - 1][0][tj] = acc0; s_part[dq - 1][1][tj] = acc1;
        s_part[dq - 1][2][tj] = acc2; s_part[dq - 1][3][tj] = acc3;
    }
    __syncthreads();
    if (dq == 0) {
        const float W = s_W;
        float* arow = attn_out + (b * NN + i0) * NN + j;
        arow[0 * NN] = W + acc0 + s_part[0][0][tj] + s_part[1][0][tj] + s_part[2][0][tj];
        arow[1 * NN] = W + acc1 + s_part[0][1][tj] + s_part[1][1][tj] + s_part[2][1][tj];
        arow[2 * NN] = W + acc2 + s_part[0][2][tj] + s_part[1][2][tj] + s_part[2][2][tj];
        arow[3 * NN] = W + acc3 + s_part[0][3][tj] + s_part[1][3][tj] + s_part[2][3][tj];
    }
}

// ---------------------------------------------------------------------------
// Kernel SO: masked softmax (4 rows) + output GEMM mirroring kA's shape:
// thread owns 2 d-cols (float2 h loads), j split 8-way (chain 64).
// grid = 256 blocks, 1024 threads.
// ---------------------------------------------------------------------------
__global__ __launch_bounds__(1024) void kSO(const int* __restrict__ mask,
                                            float* __restrict__ out,
                                            float* __restrict__ attn_out) {
    __shared__ float s_attn[4][NN];      // 8KB
    __shared__ float s_part[8][4][DM];   // 32KB: [j-group][row][d]

    const int t = threadIdx.x;
    const int blk = blockIdx.x;
    const int b = blk / (NN / 4);
    const int i0 = (blk % (NN / 4)) * 4;

    {
        const float4* src = (const float4*)(attn_out + (b * NN + i0) * NN);
        float4* dst = (float4*)&s_attn[0][0];
        for (int e = t; e < 4 * NN / 4; e += 1024) dst[e] = src[e];
    }
    __syncthreads();

    const int wid = t >> 5, lane = t & 31;
    if (wid < 4) {
        const int i = i0 + wid;
        const int4* m4 = (const int4*)(mask + (b * NN + i) * NN);
        float4* s4 = (float4*)&s_attn[wid][0];
        int4 mv[4];
        float4 sv[4];
#pragma unroll
        for (int k = 0; k < 4; k++) {
            mv[k] = m4[lane + 32 * k];
            sv[k] = s4[lane + 32 * k];
        }
        float mx = -INFINITY;
#pragma unroll
        for (int k = 0; k < 4; k++) {
            if (mv[k].x) mx = fmaxf(mx, sv[k].x);
            if (mv[k].y) mx = fmaxf(mx, sv[k].y);
            if (mv[k].z) mx = fmaxf(mx, sv[k].z);
            if (mv[k].w) mx = fmaxf(mx, sv[k].w);
        }
#pragma unroll
        for (int o = 16; o; o >>= 1) mx = fmaxf(mx, __shfl_xor_sync(0xffffffffu, mx, o));
        float sum = 0.f;
#pragma unroll
        for (int k = 0; k < 4; k++) {
            sv[k].x = mv[k].x ? __expf(sv[k].x - mx) : 0.f;
            sv[k].y = mv[k].y ? __expf(sv[k].y - mx) : 0.f;
            sv[k].z = mv[k].z ? __expf(sv[k].z - mx) : 0.f;
            sv[k].w = mv[k].w ? __expf(sv[k].w - mx) : 0.f;
            sum += sv[k].x + sv[k].y + sv[k].z + sv[k].w;
        }
#pragma unroll
        for (int o = 16; o; o >>= 1) sum += __shfl_xor_sync(0xffffffffu, sum, o);
        const float inv = (sum > 0.f) ? 1.f / sum : 0.f;
        float4* arow4 = (float4*)(attn_out + (b * NN + i) * NN);
#pragma unroll
        for (int k = 0; k < 4; k++) {
            sv[k].x *= inv; sv[k].y *= inv; sv[k].z *= inv; sv[k].w *= inv;
            s4[lane + 32 * k] = sv[k];
            arow4[lane + 32 * k] = sv[k];
        }
    }
    __syncthreads();

    // output GEMM: thread t -> cols {c2, c2+1}, j-group jg of 64 j's.
    {
        const int c2 = (t & 127) * 2;
        const int jg = t >> 7;              // 0..7
        float o00 = 0.f, o01 = 0.f, o10 = 0.f, o11 = 0.f;
        float o20 = 0.f, o21 = 0.f, o30 = 0.f, o31 = 0.f;
        const float* hb = g_h + b * NN * DM + c2;
        const float4* p0 = (const float4*)&s_attn[0][0];
        const float4* p1 = (const float4*)&s_attn[1][0];
        const float4* p2 = (const float4*)&s_attn[2][0];
        const float4* p3 = (const float4*)&s_attn[3][0];
        const int j4b = jg * 16;            // 16 float4-groups = 64 j
#pragma unroll 4
        for (int j4 = j4b; j4 < j4b + 16; j4++) {
            float2 h0 = *(const float2*)&hb[(4 * j4 + 0) * DM];
            float2 h1 = *(const float2*)&hb[(4 * j4 + 1) * DM];
            float2 h2 = *(const float2*)&hb[(4 * j4 + 2) * DM];
            float2 h3 = *(const float2*)&hb[(4 * j4 + 3) * DM];
            float4 a0 = p0[j4];             // broadcast LDS.128
            float4 a1 = p1[j4];
            float4 a2 = p2[j4];
            float4 a3 = p3[j4];
            o00 += a0.x * h0.x + a0.y * h1.x + a0.z * h2.x + a0.w * h3.x;
            o01 += a0.x * h0.y + a0.y * h1.y + a0.z * h2.y + a0.w * h3.y;
            o10 += a1.x * h0.x + a1.y * h1.x + a1.z * h2.x + a1.w * h3.x;
            o11 += a1.x * h0.y + a1.y * h1.y + a1.z * h2.y + a1.w * h3.y;
            o20 += a2.x * h0.x + a2.y * h1.x + a2.z * h2.x + a2.w * h3.x;
            o21 += a2.x * h0.y + a2.y * h1.y + a2.z * h2.y + a2.w * h3.y;
            o30 += a3.x * h0.x + a3.y * h1.x + a3.z * h2.x + a3.w * h3.x;
            o31 += a3.x * h0.y + a3.y * h1.y + a3.z * h2.y + a3.w * h3.y;
        }
        s_part[jg][0][c2] = o00; s_part[jg][0][c2 + 1] = o01;
        s_part[jg][1][c2] = o10; s_part[jg][1][c2 + 1] = o11;
        s_part[jg][2][c2] = o20; s_part[jg][2][c2 + 1] = o21;
        s_part[jg][3][c2] = o30; s_part[jg][3][c2 + 1] = o31;
    }
    __syncthreads();

    // reduce: thread t -> (row = t>>8, d = t&255)
    {
        const int r = t >> 8;
        const int d = t & (DM - 1);
        float s = 0.f;
#pragma unroll
        for (int g = 0; g < 8; g++) s += s_part[g][r][d];
        out[(b * NN + i0 + r) * DM + d] = s;
    }
}

// ---------------------------------------------------------------------------
extern "C" void kernel_launch(void* const* d_in, const int* in_sizes, int n_in,
                              void* d_out, int out_size) {
    const float* x    = (const float*)d_in[0];  // [2,512,512]
    const float* pos  = (const float*)d_in[1];  // [2,512,4]
    const int*   mask = (const int*)  d_in[2];  // [2,512,512]
    const float* Wx   = (const float*)d_in[3];  // [512,256]
    const float* bx   = (const float*)d_in[4];  // [256]
    const float* Wp   = (const float*)d_in[5];  // [4,256]
    const float* bp   = (const float*)d_in[6];  // [256]
    const float* w    = (const float*)d_in[7];  // [256]

    float* out      = (float*)d_out;            // [2,512,256]
    float* attn_out = out + BB * NN * DM;       // [2,512,512]

    kA<<<BB * NN / 4, 1024>>>(x, pos, Wx, bx, Wp, bp);
    kScore<<<(BB * NN / 4) * 4, 512>>>(w, attn_out);
    kSO<<<BB * NN / 4, 1024>>>(mask, out, attn_out);
}

// round 14
// speedup vs baseline: 1.6167x; 1.1095x over previous
#include <cuda_runtime.h>
#include <math.h>

#define BB 2
#define NN 512
#define DIN 512
#define DM 256
#define C2LOG2E 2.885390081777927f   // 2*log2(e)

typedef unsigned long long ull;

// scratch (static device globals — no allocation)
__device__ float g_h[BB * NN * DM];    // h[b][n][d] = tanh(x@Wx+bx)
__device__ float g_p[BB * NN * DM];    // P row-major: exp2(c*(u+bp))
__device__ float g_qt[BB * DM * NN];   // Q transposed: exp2(-c*u)[b][d][n]

__device__ __forceinline__ float ex2_fast(float x) {
    float y; asm("ex2.approx.f32 %0, %1;" : "=f"(y) : "f"(x)); return y;
}
__device__ __forceinline__ float rcp_fast(float x) {
    float y; asm("rcp.approx.f32 %0, %1;" : "=f"(y) : "f"(x)); return y;
}
// ---- packed f32x2 helpers (Blackwell FFMA2 path) ----
__device__ __forceinline__ ull pack2(float lo, float hi) {
    ull r; asm("mov.b64 %0, {%1, %2};" : "=l"(r) : "f"(lo), "f"(hi)); return r;
}
__device__ __forceinline__ void unpack2(ull v, float& lo, float& hi) {
    asm("mov.b64 {%0, %1}, %2;" : "=f"(lo), "=f"(hi) : "l"(v));
}
__device__ __forceinline__ ull fma2(ull a, ull b, ull c) {
    ull d; asm("fma.rn.f32x2 %0, %1, %2, %3;" : "=l"(d) : "l"(a), "l"(b), "l"(c)); return d;
}
__device__ __forceinline__ ull mul2(ull a, ull b) {
    ull d; asm("mul.rn.f32x2 %0, %1, %2;" : "=l"(d) : "l"(a), "l"(b)); return d;
}
__device__ __forceinline__ ull add2(ull a, ull b) {
    ull d; asm("add.rn.f32x2 %0, %1, %2;" : "=l"(d) : "l"(a), "l"(b)); return d;
}

// ---------------------------------------------------------------------------
// Kernel A (R11-13 best, unchanged): h = tanh(x @ Wx + bx), P/Q projections.
// ---------------------------------------------------------------------------
__global__ __launch_bounds__(1024) void kA(const float* __restrict__ x,
                                           const float* __restrict__ pos,
                                           const float* __restrict__ Wx,
                                           const float* __restrict__ bx,
                                           const float* __restrict__ Wp,
                                           const float* __restrict__ bp) {
    __shared__ float s_x[DIN][4];          // 8KB
    __shared__ float s_part[8][4][DM];     // 32KB
    const int t = threadIdx.x;
    const int row0 = blockIdx.x * 4;
    const int c2 = (t & 127) * 2;
    const int kq = t >> 7;
    const int b = row0 / NN;
    const int n0 = row0 % NN;

    if (t < DM) {
        const float w0 = Wp[0 * DM + t], w1 = Wp[1 * DM + t];
        const float w2 = Wp[2 * DM + t], w3 = Wp[3 * DM + t];
        const float bpv = bp[t];
#pragma unroll
        for (int r = 0; r < 4; r++) {
            const float* p = pos + (row0 + r) * 4;
            float u = p[0] * w0 + p[1] * w1 + p[2] * w2 + p[3] * w3;
            g_p[(row0 + r) * DM + t] = ex2_fast(C2LOG2E * (u + bpv));
            g_qt[(b * DM + t) * NN + n0 + r] = ex2_fast(-C2LOG2E * u);
        }
    }

    for (int e = t; e < DIN * 4; e += 1024) {
        int r = e >> 9, cc = e & (DIN - 1);
        s_x[cc][r] = x[(row0 + r) * DIN + cc];
    }
    __syncthreads();

    float a00 = 0.f, a01 = 0.f, a10 = 0.f, a11 = 0.f;
    float a20 = 0.f, a21 = 0.f, a30 = 0.f, a31 = 0.f;
    const int kb = kq << 6;
#pragma unroll 8
    for (int k = 0; k < 64; k++) {
        float2 wv = *(const float2*)&Wx[(kb + k) * DM + c2];
        float4 xv = *(const float4*)&s_x[kb + k][0];
        a00 += xv.x * wv.x; a01 += xv.x * wv.y;
        a10 += xv.y * wv.x; a11 += xv.y * wv.y;
        a20 += xv.z * wv.x; a21 += xv.z * wv.y;
        a30 += xv.w * wv.x; a31 += xv.w * wv.y;
    }
    s_part[kq][0][c2] = a00; s_part[kq][0][c2 + 1] = a01;
    s_part[kq][1][c2] = a10; s_part[kq][1][c2 + 1] = a11;
    s_part[kq][2][c2] = a20; s_part[kq][2][c2 + 1] = a21;
    s_part[kq][3][c2] = a30; s_part[kq][3][c2 + 1] = a31;
    __syncthreads();

    {
        const int r = t >> 8;
        const int c = t & (DM - 1);
        float s = bx[c];
#pragma unroll
        for (int g = 0; g < 8; g++) s += s_part[g][r][c];
        g_h[(row0 + r) * DM + c] = tanhf(s);
    }
}

// ---------------------------------------------------------------------------
// Kernel Score (f32x2 packed): 4 rows x 128 j per block; thread owns 2
// adjacent j's packed in a lane-pair; d split 8-way (chain 32).
// grid = (B*N/4)*4 = 1024 blocks, 512 threads (tj2 = t&63, dq = t>>6).
// Per d: 15 f32x2 fma-pipe ops cover 8 elements (4 rows x 2 j).
// ---------------------------------------------------------------------------
__global__ __launch_bounds__(512) void kScore(const float* __restrict__ w,
                                              float* __restrict__ attn_out) {
    __shared__ ull s_pib[DM][4];        // P broadcast pairs, 8KB
    __shared__ ull s_wn2[DM];           // (-2w,-2w), 2KB
    __shared__ ull s_part[7][4][64];    // dq=1..7 partials, 14KB
    __shared__ float s_W;

    const int t   = threadIdx.x;
    const int tj2 = t & 63;             // j-pair index
    const int dq  = t >> 6;             // d-eighth: 0..7
    const int jt  = blockIdx.x & 3;     // 4 j-tiles of 128
    const int it  = blockIdx.x >> 2;
    const int b   = it / (NN / 4);
    const int i0  = (it % (NN / 4)) * 4;
    const int j0  = jt * 128 + tj2 * 2; // owns j0, j0+1

    if (t < DM) {
        float wv = -2.0f * w[t];
        s_wn2[t] = pack2(wv, wv);
    }
    if (t < 32) {
        float s = 0.f;
#pragma unroll
        for (int k = 0; k < 8; k++) s += w[t + 32 * k];
#pragma unroll
        for (int o = 16; o; o >>= 1) s += __shfl_xor_sync(0xffffffffu, s, o);
        if (t == 0) s_W = s;
    }
    {
        const float* prow = g_p + (b * NN + i0) * DM;
        for (int e = t; e < 4 * DM; e += 512) {
            int r = e >> 8, d = e & (DM - 1);
            float v = prow[r * DM + d];
            s_pib[d][r] = pack2(v, v);
        }
    }
    __syncthreads();

    const ull ONE2 = pack2(1.0f, 1.0f);
    ull acc0 = 0, acc1 = 0, acc2 = 0, acc3 = 0;   // 0.0f pair == 0 bits
    const float* qp = g_qt + b * DM * NN + j0;
    const int db = dq << 5;             // 32 d per eighth
    ull qbuf[4];
#pragma unroll
    for (int p = 0; p < 4; p++) qbuf[p] = *(const ull*)(qp + (db + p) * NN);

    for (int d0 = db; d0 < db + 32; d0 += 4) {
        ull qc[4];
#pragma unroll
        for (int p = 0; p < 4; p++) qc[p] = qbuf[p];
        if (d0 + 4 < db + 32) {
#pragma unroll
            for (int p = 0; p < 4; p++) qbuf[p] = *(const ull*)(qp + (d0 + 4 + p) * NN);
        }
#pragma unroll
        for (int dd = 0; dd < 4; dd++) {
            const int d = d0 + dd;
            const ull wn2 = s_wn2[d];
            ulonglong2 piA = *(const ulonglong2*)&s_pib[d][0];  // rows 0,1 (LDS.128)
            ulonglong2 piB = *(const ulonglong2*)&s_pib[d][2];  // rows 2,3
            const ull qj2 = qc[dd];
            ull de0 = fma2(piA.x, qj2, ONE2);
            ull de1 = fma2(piA.y, qj2, ONE2);
            ull de2 = fma2(piB.x, qj2, ONE2);
            ull de3 = fma2(piB.y, qj2, ONE2);
            ull p01 = mul2(de0, de1);
            ull p23 = mul2(de2, de3);
            ull tot = mul2(p01, p23);
            float tl, th;
            unpack2(tot, tl, th);
            ull r2 = pack2(rcp_fast(tl), rcp_fast(th));
            ull i01 = mul2(r2, p23);
            ull i23 = mul2(r2, p01);
            ull w01 = mul2(wn2, i01);
            ull w23 = mul2(wn2, i23);
            acc0 = fma2(w01, de1, acc0);
            acc1 = fma2(w01, de0, acc1);
            acc2 = fma2(w23, de3, acc2);
            acc3 = fma2(w23, de2, acc3);
        }
    }
    if (dq) {
        s_part[dq - 1][0][tj2] = acc0;
        s_part[dq - 1][1][tj2] = acc1;
        s_part[dq - 1][2][tj2] = acc2;
        s_part[dq - 1][3][tj2] = acc3;
    }
    __syncthreads();
    if (dq == 0) {
        const ull W2 = pack2(s_W, s_W);
#pragma unroll
        for (int g = 0; g < 7; g++) {
            acc0 = add2(acc0, s_part[g][0][tj2]);
            acc1 = add2(acc1, s_part[g][1][tj2]);
            acc2 = add2(acc2, s_part[g][2][tj2]);
            acc3 = add2(acc3, s_part[g][3][tj2]);
        }
        float* arow = attn_out + (b * NN + i0) * NN + j0;
        *(ull*)&arow[0 * NN] = add2(acc0, W2);
        *(ull*)&arow[1 * NN] = add2(acc1, W2);
        *(ull*)&arow[2 * NN] = add2(acc2, W2);
        *(ull*)&arow[3 * NN] = add2(acc3, W2);
    }
}

// ---------------------------------------------------------------------------
// Kernel SO (R12/13 best, unchanged): masked softmax + output GEMM,
// thread owns 2 d-cols (float2 h), j split 8-way. grid 256 x 1024.
// ---------------------------------------------------------------------------
__global__ __launch_bounds__(1024) void kSO(const int* __restrict__ mask,
                                            float* __restrict__ out,
                                            float* __restrict__ attn_out) {
    __shared__ float s_attn[4][NN];      // 8KB
    __shared__ float s_part[8][4][DM];   // 32KB

    const int t = threadIdx.x;
    const int blk = blockIdx.x;
    const int b = blk / (NN / 4);
    const int i0 = (blk % (NN / 4)) * 4;

    {
        const float4* src = (const float4*)(attn_out + (b * NN + i0) * NN);
        float4* dst = (float4*)&s_attn[0][0];
        for (int e = t; e < 4 * NN / 4; e += 1024) dst[e] = src[e];
    }
    __syncthreads();

    const int wid = t >> 5, lane = t & 31;
    if (wid < 4) {
        const int i = i0 + wid;
        const int4* m4 = (const int4*)(mask + (b * NN + i) * NN);
        float4* s4 = (float4*)&s_attn[wid][0];
        int4 mv[4];
        float4 sv[4];
#pragma unroll
        for (int k = 0; k < 4; k++) {
            mv[k] = m4[lane + 32 * k];
            sv[k] = s4[lane + 32 * k];
        }
        float mx = -INFINITY;
#pragma unroll
        for (int k = 0; k < 4; k++) {
            if (mv[k].x) mx = fmaxf(mx, sv[k].x);
            if (mv[k].y) mx = fmaxf(mx, sv[k].y);
            if (mv[k].z) mx = fmaxf(mx, sv[k].z);
            if (mv[k].w) mx = fmaxf(mx, sv[k].w);
        }
#pragma unroll
        for (int o = 16; o; o >>= 1) mx = fmaxf(mx, __shfl_xor_sync(0xffffffffu, mx, o));
        float sum = 0.f;
#pragma unroll
        for (int k = 0; k < 4; k++) {
            sv[k].x = mv[k].x ? __expf(sv[k].x - mx) : 0.f;
            sv[k].y = mv[k].y ? __expf(sv[k].y - mx) : 0.f;
            sv[k].z = mv[k].z ? __expf(sv[k].z - mx) : 0.f;
            sv[k].w = mv[k].w ? __expf(sv[k].w - mx) : 0.f;
            sum += sv[k].x + sv[k].y + sv[k].z + sv[k].w;
        }
#pragma unroll
        for (int o = 16; o; o >>= 1) sum += __shfl_xor_sync(0xffffffffu, sum, o);
        const float inv = (sum > 0.f) ? 1.f / sum : 0.f;
        float4* arow4 = (float4*)(attn_out + (b * NN + i) * NN);
#pragma unroll
        for (int k = 0; k < 4; k++) {
            sv[k].x *= inv; sv[k].y *= inv; sv[k].z *= inv; sv[k].w *= inv;
            s4[lane + 32 * k] = sv[k];
            arow4[lane + 32 * k] = sv[k];
        }
    }
    __syncthreads();

    {
        const int c2 = (t & 127) * 2;
        const int jg = t >> 7;
        float o00 = 0.f, o01 = 0.f, o10 = 0.f, o11 = 0.f;
        float o20 = 0.f, o21 = 0.f, o30 = 0.f, o31 = 0.f;
        const float* hb = g_h + b * NN * DM + c2;
        const float4* p0 = (const float4*)&s_attn[0][0];
        const float4* p1 = (const float4*)&s_attn[1][0];
        const float4* p2 = (const float4*)&s_attn[2][0];
        const float4* p3 = (const float4*)&s_attn[3][0];
        const int j4b = jg * 16;
#pragma unroll 4
        for (int j4 = j4b; j4 < j4b + 16; j4++) {
            float2 h0 = *(const float2*)&hb[(4 * j4 + 0) * DM];
            float2 h1 = *(const float2*)&hb[(4 * j4 + 1) * DM];
            float2 h2 = *(const float2*)&hb[(4 * j4 + 2) * DM];
            float2 h3 = *(const float2*)&hb[(4 * j4 + 3) * DM];
            float4 a0 = p0[j4];
            float4 a1 = p1[j4];
            float4 a2 = p2[j4];
            float4 a3 = p3[j4];
            o00 += a0.x * h0.x + a0.y * h1.x + a0.z * h2.x + a0.w * h3.x;
            o01 += a0.x * h0.y + a0.y * h1.y + a0.z * h2.y + a0.w * h3.y;
            o10 += a1.x * h0.x + a1.y * h1.x + a1.z * h2.x + a1.w * h3.x;
            o11 += a1.x * h0.y + a1.y * h1.y + a1.z * h2.y + a1.w * h3.y;
            o20 += a2.x * h0.x + a2.y * h1.x + a2.z * h2.x + a2.w * h3.x;
            o21 += a2.x * h0.y + a2.y * h1.y + a2.z * h2.y + a2.w * h3.y;
            o30 += a3.x * h0.x + a3.y * h1.x + a3.z * h2.x + a3.w * h3.x;
            o31 += a3.x * h0.y + a3.y * h1.y + a3.z * h2.y + a3.w * h3.y;
        }
        s_part[jg][0][c2] = o00; s_part[jg][0][c2 + 1] = o01;
        s_part[jg][1][c2] = o10; s_part[jg][1][c2 + 1] = o11;
        s_part[jg][2][c2] = o20; s_part[jg][2][c2 + 1] = o21;
        s_part[jg][3][c2] = o30; s_part[jg][3][c2 + 1] = o31;
    }
    __syncthreads();

    {
        const int r = t >> 8;
        const int d = t & (DM - 1);
        float s = 0.f;
#pragma unroll
        for (int g = 0; g < 8; g++) s += s_part[g][r][d];
        out[(b * NN + i0 + r) * DM + d] = s;
    }
}

// ---------------------------------------------------------------------------
extern "C" void kernel_launch(void* const* d_in, const int* in_sizes, int n_in,
                              void* d_out, int out_size) {
    const float* x    = (const float*)d_in[0];  // [2,512,512]
    const float* pos  = (const float*)d_in[1];  // [2,512,4]
    const int*   mask = (const int*)  d_in[2];  // [2,512,512]
    const float* Wx   = (const float*)d_in[3];  // [512,256]
    const float* bx   = (const float*)d_in[4];  // [256]
    const float* Wp   = (const float*)d_in[5];  // [4,256]
    const float* bp   = (const float*)d_in[6];  // [256]
    const float* w    = (const float*)d_in[7];  // [256]

    float* out      = (float*)d_out;            // [2,512,256]
    float* attn_out = out + BB * NN * DM;       // [2,512,512]

    kA<<<BB * NN / 4, 1024>>>(x, pos, Wx, bx, Wp, bp);
    kScore<<<(BB * NN / 4) * 4, 512>>>(w, attn_out);
    kSO<<<BB * NN / 4, 1024>>>(mask, out, attn_out);
}